// round 1
// baseline (speedup 1.0000x reference)
#include <cuda_runtime.h>

// HierSoftmax: per-token Huffman-path NLL.
// Inputs (metadata order):
//   0: hidden     [8,1024,512] f32
//   1: node_emb   [50256,512]  f32
//   2: path_signs [50257,20]   f32
//   3: targets    [8,1024]     i32
//   4: path_nodes [50257,20]   i32
//   5: path_lens  [50257]      i32
// Output: scalar f32 = mean over tokens of -sum_{d<len} log_sigmoid(sign_d * <h, w_node_d>)

#define D_DIM     512
#define MAX_DEPTH 20
#define N_TOK     (8 * 1024)

__device__ float g_partials[N_TOK];

__global__ __launch_bounds__(128, 16)
void hs_main_kernel(const float* __restrict__ hidden,
                    const float* __restrict__ node_emb,
                    const float* __restrict__ path_signs,
                    const int*   __restrict__ targets,
                    const int*   __restrict__ path_nodes,
                    const int*   __restrict__ path_lens)
{
    const int tok  = blockIdx.x;
    const int tid  = threadIdx.x;
    const int warp = tid >> 5;
    const int lane = tid & 31;

    const int t = __ldg(&targets[tok]);
    int len = __ldg(&path_lens[t]);
    if (len < 1) len = 1;            // reference: max(path_lens, 1)

    // Hidden row, register-resident: lane holds elems {lane*4+k*... } via 4 float4s.
    const float4* h4 = reinterpret_cast<const float4*>(hidden + (size_t)tok * D_DIM);
    const float4 h0 = h4[lane];
    const float4 h1 = h4[lane + 32];
    const float4 h2 = h4[lane + 64];
    const float4 h3 = h4[lane + 96];

    float local = 0.0f;

    // Each warp takes depths d = warp, warp+4, ...
    for (int d = warp; d < len; d += 4) {
        const int   node = __ldg(&path_nodes[t * MAX_DEPTH + d]);
        const float ps   = __ldg(&path_signs[t * MAX_DEPTH + d]);

        const float4* w4 = reinterpret_cast<const float4*>(node_emb + (size_t)node * D_DIM);
        const float4 w0 = w4[lane];
        const float4 w1 = w4[lane + 32];
        const float4 w2 = w4[lane + 64];
        const float4 w3 = w4[lane + 96];

        float dot;
        {
            float a = h0.x * w0.x;  a = fmaf(h0.y, w0.y, a);
            a = fmaf(h0.z, w0.z, a); a = fmaf(h0.w, w0.w, a);
            float b = h1.x * w1.x;  b = fmaf(h1.y, w1.y, b);
            b = fmaf(h1.z, w1.z, b); b = fmaf(h1.w, w1.w, b);
            float c = h2.x * w2.x;  c = fmaf(h2.y, w2.y, c);
            c = fmaf(h2.z, w2.z, c); c = fmaf(h2.w, w2.w, c);
            float e = h3.x * w3.x;  e = fmaf(h3.y, w3.y, e);
            e = fmaf(h3.z, w3.z, e); e = fmaf(h3.w, w3.w, e);
            dot = (a + b) + (c + e);
        }
        // butterfly warp reduce: all lanes end with full dot
        #pragma unroll
        for (int off = 16; off > 0; off >>= 1)
            dot += __shfl_xor_sync(0xffffffffu, dot, off);

        // sign = +1 if ps >= 0 else -1 ; term = -log_sigmoid(sign*dot) = softplus(-sign*dot)
        const float y  = (ps >= 0.0f) ? -dot : dot;
        const float sp = fmaxf(y, 0.0f) + log1pf(__expf(-fabsf(y)));
        local += sp;   // identical across lanes (post-reduce), take lane 0 below
    }

    __shared__ float wsum[4];
    if (lane == 0) wsum[warp] = local;
    __syncthreads();
    if (tid == 0)
        g_partials[tok] = (wsum[0] + wsum[1]) + (wsum[2] + wsum[3]);
}

__global__ __launch_bounds__(256)
void hs_finalize_kernel(float* __restrict__ out)
{
    const int tid = threadIdx.x;
    float s = 0.0f;
    #pragma unroll
    for (int i = tid; i < N_TOK; i += 256)
        s += g_partials[i];

    #pragma unroll
    for (int off = 16; off > 0; off >>= 1)
        s += __shfl_xor_sync(0xffffffffu, s, off);

    __shared__ float ws[8];
    if ((tid & 31) == 0) ws[tid >> 5] = s;
    __syncthreads();
    if (tid == 0) {
        float tot = 0.0f;
        #pragma unroll
        for (int w = 0; w < 8; w++) tot += ws[w];
        out[0] = tot / (float)N_TOK;
    }
}

extern "C" void kernel_launch(void* const* d_in, const int* in_sizes, int n_in,
                              void* d_out, int out_size)
{
    const float* hidden     = (const float*)d_in[0];
    const float* node_emb   = (const float*)d_in[1];
    const float* path_signs = (const float*)d_in[2];
    const int*   targets    = (const int*)  d_in[3];
    const int*   path_nodes = (const int*)  d_in[4];
    const int*   path_lens  = (const int*)  d_in[5];
    float* out = (float*)d_out;

    hs_main_kernel<<<N_TOK, 128>>>(hidden, node_emb, path_signs,
                                   targets, path_nodes, path_lens);
    hs_finalize_kernel<<<1, 256>>>(out);
}